// round 2
// baseline (speedup 1.0000x reference)
#include <cuda_runtime.h>

typedef unsigned long long u64;

#define B_ 64
#define T_ 100
#define N_ 25
#define V_ 128
#define C_ 128
#define E_ 64
#define G_ (B_*T_)          // 6400 graphs
#define GPB 4               // graphs per block
#define ROWS (GPB*N_)       // 100
#define NBLOCKS (G_/GPB)    // 1600
#define PITCH 132           // padded smem pitch (floats)

// Scratch (no allocation allowed -> device globals)
__device__ float g_A2[N_*N_];
__device__ float g_rows[N_];
__device__ float g_bvec[C_];
__device__ float g_W12[V_*C_];
__device__ float g_sum[T_];
__device__ float g_sumsq[T_];
__device__ float g_scale[T_];
__device__ float g_shift[T_];

// ---------------------------------------------------------------------------
// K0: build normalized adjacency A, A^2, row-sums of A, b1@W2; zero BN accums.
// Handles edge_index stored as int64 OR int32 (JAX x64 ambiguity).
// ---------------------------------------------------------------------------
__global__ void prep_kernel(const int* __restrict__ eiw,
                            const float* __restrict__ W2,
                            const float* __restrict__ b1) {
    __shared__ float sA[N_*N_];
    __shared__ float sdis[N_];
    __shared__ int s_is64;
    int tid = threadIdx.x;  // 128 threads

    if (tid == 0) {
        // If int64: first 128 words are 64 little-endian (lo,hi) pairs with hi==0.
        // If int32: words are 128 random values in [0,25); all-odd-zero is ~impossible.
        int all0 = 1;
        for (int e = 0; e < E_; e++) if (eiw[2*e + 1] != 0) all0 = 0;
        s_is64 = all0;
    }
    if (tid < T_) { g_sum[tid] = 0.f; g_sumsq[tid] = 0.f; }
    for (int i = tid; i < N_*N_; i += blockDim.x) sA[i] = 0.f;
    __syncthreads();
    int is64 = s_is64;

    if (tid < N_) {
        int deg = 1;  // self loop
        for (int e = 0; e < E_; e++) {
            int t = is64 ? eiw[2*(E_+e)] : eiw[E_+e];
            if (t == tid) deg++;
        }
        sdis[tid] = rsqrtf((float)deg);
    }
    __syncthreads();
    if (tid < N_) atomicAdd(&sA[tid*N_ + tid], sdis[tid]*sdis[tid]);
    if (tid < E_) {
        int s = is64 ? eiw[2*tid]        : eiw[tid];
        int t = is64 ? eiw[2*(E_+tid)]   : eiw[E_+tid];
        atomicAdd(&sA[t*N_ + s], sdis[s]*sdis[t]);
    }
    __syncthreads();

    for (int i = tid; i < N_*N_; i += blockDim.x) {
        int r = i / N_, c = i - r*N_;
        float acc = 0.f;
        for (int m = 0; m < N_; m++) acc += sA[r*N_+m] * sA[m*N_+c];
        g_A2[i] = acc;
    }
    if (tid < N_) {
        float acc = 0.f;
        for (int m = 0; m < N_; m++) acc += sA[tid*N_+m];
        g_rows[tid] = acc;
    }
    if (tid < C_) {
        float acc = 0.f;
        for (int k = 0; k < C_; k++) acc += b1[k] * W2[k*C_ + tid];
        g_bvec[tid] = acc;
    }
}

// ---------------------------------------------------------------------------
// K1: W12 = W1 @ W2  (128x128x128)
// ---------------------------------------------------------------------------
__global__ void w12_kernel(const float* __restrict__ W1,
                           const float* __restrict__ W2) {
    int v = blockIdx.x, j = threadIdx.x;
    float acc = 0.f;
    #pragma unroll 8
    for (int k = 0; k < C_; k++) acc += W1[v*C_ + k] * W2[k*C_ + j];
    g_W12[v*C_ + j] = acc;
}

// ---------------------------------------------------------------------------
// K2: H2 = A2 @ (X @ W12) + rows(A)*bvec + b2, fused with BN sum/sumsq atomics.
// 400 threads = (16, 25); each thread: rows 4*ty..4*ty+3, cols {4tx..4tx+3, 64+4tx..64+4tx+3}.
// GEMM inner loop uses packed fma.rn.f32x2 (2 FMA per issue slot).
// ---------------------------------------------------------------------------
extern __shared__ float smem[];

__global__ void __launch_bounds__(400, 1)
gcn_main(const float* __restrict__ x, const float* __restrict__ b2,
         float* __restrict__ out) {
    float* sW  = smem;                   // 16384 floats
    float* sX  = smem + V_*C_;           // ROWS*PITCH floats (reused as sY)
    float* sA2 = sX + ROWS*PITCH;        // 625 floats
    __shared__ float sPart[GPB][2];

    int tx = threadIdx.x, ty = threadIdx.y;
    int tid = ty*16 + tx;

    // stage W12 + A2
    for (int i = tid; i < (V_*C_)/4; i += 400)
        ((float4*)sW)[i] = ((const float4*)g_W12)[i];
    for (int i = tid; i < N_*N_; i += 400) sA2[i] = g_A2[i];
    if (tid < GPB*2) (&sPart[0][0])[tid] = 0.f;

    // stage X tile [100][128] with pitch 132
    const float* xg = x + (size_t)blockIdx.x * (ROWS*C_);
    for (int i = tid; i < (ROWS*C_)/4; i += 400) {
        int r = i >> 5, c4 = i & 31;
        float4 v = ((const float4*)xg)[i];
        *(float4*)(sX + r*PITCH + c4*4) = v;
    }
    __syncthreads();

    int r0 = 4*ty;
    u64 acc[4][4];
    #pragma unroll
    for (int i = 0; i < 4; i++)
        #pragma unroll
        for (int j = 0; j < 4; j++) acc[i][j] = 0ull;

    const float* wb = sW + 4*tx;
    #pragma unroll 4
    for (int k = 0; k < C_; k++) {
        const float* wr = wb + k*C_;
        u64 w0 = *(const u64*)(wr + 0);
        u64 w1 = *(const u64*)(wr + 2);
        u64 w2 = *(const u64*)(wr + 64);
        u64 w3 = *(const u64*)(wr + 66);
        #pragma unroll
        for (int i = 0; i < 4; i++) {
            float xv = sX[(r0 + i)*PITCH + k];
            u64 xp;
            asm("mov.b64 %0, {%1, %1};" : "=l"(xp) : "f"(xv));
            asm("fma.rn.f32x2 %0, %1, %2, %0;" : "+l"(acc[i][0]) : "l"(xp), "l"(w0));
            asm("fma.rn.f32x2 %0, %1, %2, %0;" : "+l"(acc[i][1]) : "l"(xp), "l"(w1));
            asm("fma.rn.f32x2 %0, %1, %2, %0;" : "+l"(acc[i][2]) : "l"(xp), "l"(w2));
            asm("fma.rn.f32x2 %0, %1, %2, %0;" : "+l"(acc[i][3]) : "l"(xp), "l"(w3));
        }
    }
    __syncthreads();   // everyone done reading sX

    // spill Y = X@W12 into smem (reuse sX region)
    #pragma unroll
    for (int i = 0; i < 4; i++) {
        float* yr = sX + (r0 + i)*PITCH;
        *(u64*)(yr + 4*tx + 0)  = acc[i][0];
        *(u64*)(yr + 4*tx + 2)  = acc[i][1];
        *(u64*)(yr + 64 + 4*tx) = acc[i][2];
        *(u64*)(yr + 66 + 4*tx) = acc[i][3];
    }
    __syncthreads();

    // epilogue: H = A2 @ Y + rows[n]*bvec + b2, plus BN partials
    float4 bv0 = *(const float4*)(g_bvec + 4*tx);
    float4 bv1 = *(const float4*)(g_bvec + 64 + 4*tx);
    float4 bb0 = *(const float4*)(b2 + 4*tx);
    float4 bb1 = *(const float4*)(b2 + 64 + 4*tx);

    int gA = r0 / N_;
    int gB = (r0 + 3) / N_;
    for (int g = gA; g <= gB; ++g) {
        float h[4][8];
        int   nn[4];
        bool  val[4];
        #pragma unroll
        for (int i = 0; i < 4; i++) {
            int n = r0 + i - g*N_;
            val[i] = (n >= 0) && (n < N_);
            nn[i]  = min(max(n, 0), N_-1);
            float rw = val[i] ? g_rows[nn[i]] : 0.f;
            h[i][0] = rw*bv0.x + bb0.x; h[i][1] = rw*bv0.y + bb0.y;
            h[i][2] = rw*bv0.z + bb0.z; h[i][3] = rw*bv0.w + bb0.w;
            h[i][4] = rw*bv1.x + bb1.x; h[i][5] = rw*bv1.y + bb1.y;
            h[i][6] = rw*bv1.z + bb1.z; h[i][7] = rw*bv1.w + bb1.w;
        }
        const float* yb = sX + g*N_*PITCH;
        #pragma unroll
        for (int m = 0; m < N_; m++) {
            float4 y0 = *(const float4*)(yb + m*PITCH + 4*tx);
            float4 y1 = *(const float4*)(yb + m*PITCH + 64 + 4*tx);
            #pragma unroll
            for (int i = 0; i < 4; i++) {
                float a = val[i] ? sA2[nn[i]*N_ + m] : 0.f;
                h[i][0] += a*y0.x; h[i][1] += a*y0.y;
                h[i][2] += a*y0.z; h[i][3] += a*y0.w;
                h[i][4] += a*y1.x; h[i][5] += a*y1.y;
                h[i][6] += a*y1.z; h[i][7] += a*y1.w;
            }
        }
        float ps = 0.f, ps2 = 0.f;
        #pragma unroll
        for (int i = 0; i < 4; i++) {
            if (!val[i]) continue;
            float* og = out + ((size_t)blockIdx.x*ROWS + (r0 + i))*C_;
            *(float4*)(og + 4*tx)      = make_float4(h[i][0], h[i][1], h[i][2], h[i][3]);
            *(float4*)(og + 64 + 4*tx) = make_float4(h[i][4], h[i][5], h[i][6], h[i][7]);
            #pragma unroll
            for (int j = 0; j < 8; j++) { ps += h[i][j]; ps2 += h[i][j]*h[i][j]; }
        }
        atomicAdd(&sPart[g][0], ps);
        atomicAdd(&sPart[g][1], ps2);
    }
    __syncthreads();
    if (tid < GPB) {
        int t = (blockIdx.x*GPB + tid) % T_;
        atomicAdd(&g_sum[t],   sPart[tid][0]);
        atomicAdd(&g_sumsq[t], sPart[tid][1]);
    }
}

// ---------------------------------------------------------------------------
// K3: fold BN stats + gamma/beta into per-t scale/shift
// ---------------------------------------------------------------------------
__global__ void stats_kernel(const float* __restrict__ gamma,
                             const float* __restrict__ beta) {
    int t = threadIdx.x;
    if (t < T_) {
        const float inv_cnt = 1.0f / (float)(B_*N_*C_);
        float mean = g_sum[t] * inv_cnt;
        float var  = g_sumsq[t] * inv_cnt - mean*mean;
        float sc   = rsqrtf(var + 1e-5f) * gamma[t];
        g_scale[t] = sc;
        g_shift[t] = beta[t] - mean*sc;
    }
}

// ---------------------------------------------------------------------------
// K4: in-place normalize + relu  (t = (idx/3200) % 100, float4-vectorized)
// ---------------------------------------------------------------------------
__global__ void norm_kernel(float* __restrict__ out) {
    int i = blockIdx.x*blockDim.x + threadIdx.x;   // float4 index, exact grid
    int t = (i / 800) % T_;                        // 800 float4 per (b,t)-slab
    float sc = g_scale[t], sh = g_shift[t];
    float4 v = ((float4*)out)[i];
    v.x = fmaxf(fmaf(v.x, sc, sh), 0.f);
    v.y = fmaxf(fmaf(v.y, sc, sh), 0.f);
    v.z = fmaxf(fmaf(v.z, sc, sh), 0.f);
    v.w = fmaxf(fmaf(v.w, sc, sh), 0.f);
    ((float4*)out)[i] = v;
}

// ---------------------------------------------------------------------------
extern "C" void kernel_launch(void* const* d_in, const int* in_sizes, int n_in,
                              void* d_out, int out_size) {
    const float* x     = (const float*)d_in[0];
    const int*   eiw   = (const int*)  d_in[1];   // int64 or int32 words, sniffed
    const float* W1    = (const float*)d_in[2];
    const float* b1    = (const float*)d_in[3];
    const float* W2    = (const float*)d_in[4];
    const float* b2    = (const float*)d_in[5];
    const float* gamma = (const float*)d_in[6];
    const float* beta  = (const float*)d_in[7];
    float* out = (float*)d_out;

    const int smem_bytes = (V_*C_ + ROWS*PITCH + N_*N_) * (int)sizeof(float);
    cudaFuncSetAttribute(gcn_main, cudaFuncAttributeMaxDynamicSharedMemorySize,
                         smem_bytes);

    prep_kernel<<<1, 128>>>(eiw, W2, b1);
    w12_kernel<<<C_, C_>>>(W1, W2);
    gcn_main<<<NBLOCKS, dim3(16, 25), smem_bytes>>>(x, b2, out);
    stats_kernel<<<1, 128>>>(gamma, beta);
    norm_kernel<<<(G_*N_*C_)/4/256, 256>>>(out);
}

// round 6
// speedup vs baseline: 1.2839x; 1.2839x over previous
#include <cuda_runtime.h>
#include <cuda_bf16.h>

typedef unsigned int u32;
typedef unsigned long long u64;

#define B_ 64
#define T_ 100
#define N_ 25
#define V_ 128
#define C_ 128
#define E_ 64
#define G_ (B_*T_)
#define GPB 5
#define ROWS (GPB*N_)        // 125
#define NBLOCKS (G_/GPB)     // 1280

// bf16 images: [128 rows][136 cols] (pitch 272 bytes), 34816 B each
#define IPITCH 272
#define IMGB 34816
#define IMGW (IMGB/4)        // 8704 u32

// dynamic smem: A2H, A2L, XH(->ZH), XL(->ZL), WH, WL
#define OFF_A2H 0
#define OFF_A2L IMGB
#define OFF_XH  (2*IMGB)
#define OFF_XL  (3*IMGB)
#define OFF_WH  (4*IMGB)
#define OFF_WL  (5*IMGB)
#define DSMEM_BYTES (6*IMGB)   // 208896

// -------------------------- device scratch ---------------------------------
__device__ __align__(16) u32 g_A2dhi[IMGW];
__device__ __align__(16) u32 g_A2dlo[IMGW];
__device__ __align__(16) u32 g_Whi[IMGW];
__device__ __align__(16) u32 g_Wlo[IMGW];
__device__ float g_rows[N_];
__device__ float g_bvec[C_];
__device__ float g_sum[T_];
__device__ float g_sumsq[T_];
__device__ float g_scale[T_];
__device__ float g_shift[T_];

// -------------------------- helpers ----------------------------------------
__device__ __forceinline__ u32 smem_u32(const void* p) {
    u32 a;
    asm("{ .reg .u64 t; cvta.to.shared.u64 t, %1; cvt.u32.u64 %0, t; }"
        : "=r"(a) : "l"(p));
    return a;
}
__device__ __forceinline__ u32 pack_bf2(float a, float b) {
    __nv_bfloat162 t = __floats2bfloat162_rn(a, b);
    return *reinterpret_cast<u32*>(&t);
}
__device__ __forceinline__ float bf_rt(float a) {
    return __bfloat162float(__float2bfloat16(a));
}

#define LDSM4(r0,r1,r2,r3, addr) \
    asm volatile("ldmatrix.sync.aligned.m8n8.x4.shared.b16 {%0,%1,%2,%3}, [%4];" \
        : "=r"(r0),"=r"(r1),"=r"(r2),"=r"(r3) : "r"(addr))
#define LDSM4T(r0,r1,r2,r3, addr) \
    asm volatile("ldmatrix.sync.aligned.m8n8.x4.trans.shared.b16 {%0,%1,%2,%3}, [%4];" \
        : "=r"(r0),"=r"(r1),"=r"(r2),"=r"(r3) : "r"(addr))
#define MMA16816(c, a, b) \
    asm volatile("mma.sync.aligned.m16n8k16.row.col.f32.bf16.bf16.f32 " \
        "{%0,%1,%2,%3},{%4,%5,%6,%7},{%8,%9},{%0,%1,%2,%3};" \
        : "+f"((c)[0]),"+f"((c)[1]),"+f"((c)[2]),"+f"((c)[3]) \
        : "r"((a)[0]),"r"((a)[1]),"r"((a)[2]),"r"((a)[3]), \
          "r"((b)[0]),"r"((b)[1]))

// hi/lo 3-product GEMM: C += (Ah+Al)@(Bh+Bl) approx (drop Al*Bl).
// Warp (wm 0..3, wn 0..1): rows 32wm..+31, cols 64wn..+63.
__device__ __forceinline__ void gemm_hl(u32 uAh, u32 uAl, u32 uBh, u32 uBl,
                                        int lane, int wm, int wn,
                                        float (&c)[2][8][4]) {
    const int ra = (lane & 7) + 8*((lane >> 3) & 1);  // row lane offset 0..15
    const int cb = 8*(lane >> 4);                     // col lane offset 0/8
    for (int k = 0; k < 8; k++) {
        const int k0 = 16*k;
        u32 ah[2][4], al[2][4], bh[8][2], bl[8][2];
        #pragma unroll
        for (int mt = 0; mt < 2; mt++) {
            u32 off = (u32)((32*wm + 16*mt + ra)*IPITCH + (k0 + cb)*2);
            LDSM4(ah[mt][0],ah[mt][1],ah[mt][2],ah[mt][3], uAh + off);
            LDSM4(al[mt][0],al[mt][1],al[mt][2],al[mt][3], uAl + off);
        }
        #pragma unroll
        for (int j = 0; j < 4; j++) {
            u32 off = (u32)((k0 + ra)*IPITCH + (64*wn + 16*j + cb)*2);
            LDSM4T(bh[2*j][0],bh[2*j][1],bh[2*j+1][0],bh[2*j+1][1], uBh + off);
            LDSM4T(bl[2*j][0],bl[2*j][1],bl[2*j+1][0],bl[2*j+1][1], uBl + off);
        }
        #pragma unroll
        for (int mt = 0; mt < 2; mt++)
            #pragma unroll
            for (int nt = 0; nt < 8; nt++) {
                MMA16816(c[mt][nt], ah[mt], bh[nt]);
                MMA16816(c[mt][nt], ah[mt], bl[nt]);
                MMA16816(c[mt][nt], al[mt], bh[nt]);
            }
    }
}

// ---------------------------------------------------------------------------
// K0: adjacency -> A^2 -> block-diag bf16 hi/lo images; rows(A); b1@W2; BN zero.
// ---------------------------------------------------------------------------
__global__ void prep_kernel(const int* __restrict__ eiw,
                            const float* __restrict__ W2,
                            const float* __restrict__ b1) {
    __shared__ float sA[N_*N_];
    __shared__ float sA2[N_*N_];
    __shared__ float sdis[N_];
    __shared__ int s_is64;
    int tid = threadIdx.x;   // 128

    if (tid == 0) {
        int all0 = 1;
        for (int e = 0; e < E_; e++) if (eiw[2*e + 1] != 0) all0 = 0;
        s_is64 = all0;
    }
    if (tid < T_) { g_sum[tid] = 0.f; g_sumsq[tid] = 0.f; }
    for (int i = tid; i < N_*N_; i += blockDim.x) sA[i] = 0.f;
    __syncthreads();
    int is64 = s_is64;

    if (tid < N_) {
        int deg = 1;
        for (int e = 0; e < E_; e++) {
            int t = is64 ? eiw[2*(E_+e)] : eiw[E_+e];
            if (t == tid) deg++;
        }
        sdis[tid] = rsqrtf((float)deg);
    }
    __syncthreads();
    if (tid < N_) atomicAdd(&sA[tid*N_ + tid], sdis[tid]*sdis[tid]);
    if (tid < E_) {
        int s = is64 ? eiw[2*tid]      : eiw[tid];
        int t = is64 ? eiw[2*(E_+tid)] : eiw[E_+tid];
        atomicAdd(&sA[t*N_ + s], sdis[s]*sdis[t]);
    }
    __syncthreads();

    for (int i = tid; i < N_*N_; i += blockDim.x) {
        int r = i / N_, c = i - r*N_;
        float acc = 0.f;
        for (int m = 0; m < N_; m++) acc += sA[r*N_+m] * sA[m*N_+c];
        sA2[i] = acc;
    }
    if (tid < N_) {
        float acc = 0.f;
        for (int m = 0; m < N_; m++) acc += sA[tid*N_+m];
        g_rows[tid] = acc;
    }
    if (tid < C_) {
        float acc = 0.f;
        for (int k = 0; k < C_; k++) acc += b1[k] * W2[k*C_ + tid];
        g_bvec[tid] = acc;
    }
    __syncthreads();

    // block-diag(A2) as bf16 hi/lo padded images [128][136]
    for (int i = tid; i < IMGW; i += blockDim.x) {
        int byt = 4*i;
        int r = byt / IPITCH;
        int c0 = (byt % IPITCH) / 2;          // even
        float v0 = 0.f, v1 = 0.f;
        if (r < ROWS) {
            int g = r / N_, rn = r - g*N_, gb = g*N_;
            int cc0 = c0, cc1 = c0 + 1;
            if (cc0 >= gb && cc0 < gb + N_) v0 = sA2[rn*N_ + (cc0 - gb)];
            if (cc1 >= gb && cc1 < gb + N_) v1 = sA2[rn*N_ + (cc1 - gb)];
        }
        float h0 = bf_rt(v0), h1 = bf_rt(v1);
        g_A2dhi[i] = pack_bf2(h0, h1);
        g_A2dlo[i] = pack_bf2(v0 - h0, v1 - h1);
    }
}

// ---------------------------------------------------------------------------
// K1: W12 = W1@W2 -> bf16 hi/lo padded images (row v, col j)
// ---------------------------------------------------------------------------
__global__ void w12_kernel(const float* __restrict__ W1,
                           const float* __restrict__ W2) {
    int j = blockIdx.x, v = threadIdx.x;
    float acc = 0.f;
    #pragma unroll 8
    for (int k = 0; k < C_; k++) acc += W1[v*C_ + k] * W2[k*C_ + j];
    __nv_bfloat16 h = __float2bfloat16(acc);
    float hf = __bfloat162float(h);
    ((__nv_bfloat16*)g_Whi)[v*136 + j] = h;
    ((__nv_bfloat16*)g_Wlo)[v*136 + j] = __float2bfloat16(acc - hf);
}

// ---------------------------------------------------------------------------
// K2: per CTA (5 graphs = 125 rows, padded to 128):
//   Z = BD(A2) @ X   (HMMA bf16 hi/lo, fp32 accum)
//   H = Z @ W12      (HMMA bf16 hi/lo, fp32 accum)
//   epilogue: + rows(A)*bvec + b2, BN partials, stores (all from registers)
// ---------------------------------------------------------------------------
extern __shared__ float4 dsm4[];

__global__ void __launch_bounds__(256, 1)
gcn_mma(const float* __restrict__ x, const float* __restrict__ b2,
        float* __restrict__ out) {
    __shared__ float sRows[N_];
    __shared__ float sBv[C_];
    __shared__ float sB2[C_];
    __shared__ float sPart[GPB][2];

    char* base = (char*)dsm4;
    const int tid  = threadIdx.x;
    const int lane = tid & 31;
    const int wid  = tid >> 5;
    const int wm = wid >> 1, wn = wid & 1;

    // ---- stage ------------------------------------------------------------
    if (tid < N_) sRows[tid] = g_rows[tid];
    if (tid < C_) { sBv[tid] = g_bvec[tid]; sB2[tid] = b2[tid]; }
    if (tid < GPB*2) (&sPart[0][0])[tid] = 0.f;

    for (int i = tid; i < IMGW/4; i += 256) {
        ((float4*)(base + OFF_A2H))[i] = ((const float4*)g_A2dhi)[i];
        ((float4*)(base + OFF_A2L))[i] = ((const float4*)g_A2dlo)[i];
        ((float4*)(base + OFF_WH ))[i] = ((const float4*)g_Whi)[i];
        ((float4*)(base + OFF_WL ))[i] = ((const float4*)g_Wlo)[i];
    }
    // X -> bf16 hi/lo images (rows 0..124)
    {
        const float4* xg4 = (const float4*)(x + (size_t)blockIdx.x * (ROWS*C_));
        char* XH = base + OFF_XH;
        char* XL = base + OFF_XL;
        for (int i = tid; i < ROWS*32; i += 256) {
            int r = i >> 5, c4 = i & 31;
            float4 v = xg4[i];
            float hx = bf_rt(v.x), hy = bf_rt(v.y), hz = bf_rt(v.z), hw = bf_rt(v.w);
            char* ph = XH + r*IPITCH + 8*c4;
            char* pl = XL + r*IPITCH + 8*c4;
            *(u32*)(ph)     = pack_bf2(hx, hy);
            *(u32*)(ph + 4) = pack_bf2(hz, hw);
            *(u32*)(pl)     = pack_bf2(v.x - hx, v.y - hy);
            *(u32*)(pl + 4) = pack_bf2(v.z - hz, v.w - hw);
        }
        // zero pad rows 125..127 (read by k-loop; must not be NaN garbage)
        for (int i = tid; i < 2*204; i += 256) {
            int im = i / 204, o = i - im*204;
            *(u32*)(base + (im ? OFF_XL : OFF_XH) + ROWS*IPITCH + 4*o) = 0;
        }
    }
    __syncthreads();

    const u32 uA2H = smem_u32(base + OFF_A2H), uA2L = smem_u32(base + OFF_A2L);
    const u32 uXH  = smem_u32(base + OFF_XH),  uXL  = smem_u32(base + OFF_XL);
    const u32 uWH  = smem_u32(base + OFF_WH),  uWL  = smem_u32(base + OFF_WL);

    // ---- GEMM1: Z = BD(A2) @ X -------------------------------------------
    float c[2][8][4];
    #pragma unroll
    for (int mt = 0; mt < 2; mt++)
        #pragma unroll
        for (int nt = 0; nt < 8; nt++)
            #pragma unroll
            for (int q = 0; q < 4; q++) c[mt][nt][q] = 0.f;

    gemm_hl(uA2H, uA2L, uXH, uXL, lane, wm, wn, c);
    __syncthreads();   // all warps done reading X images

    // ---- convert Z -> bf16 hi/lo, overwrite X images ----------------------
    {
        char* ZH = base + OFF_XH;
        char* ZL = base + OFF_XL;
        #pragma unroll
        for (int mt = 0; mt < 2; mt++)
            #pragma unroll
            for (int h = 0; h < 2; h++) {
                int r = 32*wm + 16*mt + 8*h + (lane >> 2);
                #pragma unroll
                for (int nt = 0; nt < 8; nt++) {
                    int c0 = 64*wn + 8*nt + 2*(lane & 3);
                    float v0 = c[mt][nt][2*h], v1 = c[mt][nt][2*h + 1];
                    float h0 = bf_rt(v0), h1 = bf_rt(v1);
                    *(u32*)(ZH + r*IPITCH + 2*c0) = pack_bf2(h0, h1);
                    *(u32*)(ZL + r*IPITCH + 2*c0) = pack_bf2(v0 - h0, v1 - h1);
                }
            }
    }
    __syncthreads();

    // ---- GEMM2: H = Z @ W12 ----------------------------------------------
    #pragma unroll
    for (int mt = 0; mt < 2; mt++)
        #pragma unroll
        for (int nt = 0; nt < 8; nt++)
            #pragma unroll
            for (int q = 0; q < 4; q++) c[mt][nt][q] = 0.f;

    gemm_hl(uXH, uXL, uWH, uWL, lane, wm, wn, c);

    // ---- epilogue: bias + BN partials + stores ----------------------------
    // NOTE: warp-collective shuffles are executed UNCONDITIONALLY (inactive
    // rows contribute 0); only stores/atomics are predicated. The previous
    // revision had the shfl inside `if (r < ROWS)` -> divergent full-mask
    // shuffle -> device hang.
    float* og = out + (size_t)blockIdx.x * (ROWS*C_);
    #pragma unroll
    for (int mt = 0; mt < 2; mt++)
        #pragma unroll
        for (int h = 0; h < 2; h++) {
            int r = 32*wm + 16*mt + 8*h + (lane >> 2);
            bool act = (r < ROWS);
            int rr = act ? r : 0;
            int g = rr / N_;
            float rw = act ? sRows[rr - g*N_] : 0.f;
            float s = 0.f, s2 = 0.f;
            #pragma unroll
            for (int nt = 0; nt < 8; nt++) {
                int c0 = 64*wn + 8*nt + 2*(lane & 3);
                float v0 = c[mt][nt][2*h]     + rw*sBv[c0]   + sB2[c0];
                float v1 = c[mt][nt][2*h + 1] + rw*sBv[c0+1] + sB2[c0+1];
                if (act) {
                    *(float2*)(og + r*C_ + c0) = make_float2(v0, v1);
                    s  += v0 + v1;
                    s2 += v0*v0 + v1*v1;
                }
            }
            s  += __shfl_xor_sync(0xFFFFFFFFu, s, 1);
            s  += __shfl_xor_sync(0xFFFFFFFFu, s, 2);
            s2 += __shfl_xor_sync(0xFFFFFFFFu, s2, 1);
            s2 += __shfl_xor_sync(0xFFFFFFFFu, s2, 2);
            if (act && (lane & 3) == 0) {
                atomicAdd(&sPart[g][0], s);
                atomicAdd(&sPart[g][1], s2);
            }
        }
    __syncthreads();
    if (tid < GPB) {
        int t = (blockIdx.x*GPB + tid) % T_;
        atomicAdd(&g_sum[t],   sPart[tid][0]);
        atomicAdd(&g_sumsq[t], sPart[tid][1]);
    }
}

// ---------------------------------------------------------------------------
// K3: fold BN stats + gamma/beta into per-t scale/shift
// ---------------------------------------------------------------------------
__global__ void stats_kernel(const float* __restrict__ gamma,
                             const float* __restrict__ beta) {
    int t = threadIdx.x;
    if (t < T_) {
        const float inv_cnt = 1.0f / (float)(B_*N_*C_);
        float mean = g_sum[t] * inv_cnt;
        float var  = g_sumsq[t] * inv_cnt - mean*mean;
        float sc   = rsqrtf(var + 1e-5f) * gamma[t];
        g_scale[t] = sc;
        g_shift[t] = beta[t] - mean*sc;
    }
}

// ---------------------------------------------------------------------------
// K4: in-place normalize + relu (float4)
// ---------------------------------------------------------------------------
__global__ void norm_kernel(float* __restrict__ out) {
    int i = blockIdx.x*blockDim.x + threadIdx.x;
    int t = (i / 800) % T_;
    float sc = g_scale[t], sh = g_shift[t];
    float4 v = ((float4*)out)[i];
    v.x = fmaxf(fmaf(v.x, sc, sh), 0.f);
    v.y = fmaxf(fmaf(v.y, sc, sh), 0.f);
    v.z = fmaxf(fmaf(v.z, sc, sh), 0.f);
    v.w = fmaxf(fmaf(v.w, sc, sh), 0.f);
    ((float4*)out)[i] = v;
}

// ---------------------------------------------------------------------------
extern "C" void kernel_launch(void* const* d_in, const int* in_sizes, int n_in,
                              void* d_out, int out_size) {
    const float* x     = (const float*)d_in[0];
    const int*   eiw   = (const int*)  d_in[1];
    const float* W1    = (const float*)d_in[2];
    const float* b1    = (const float*)d_in[3];
    const float* W2    = (const float*)d_in[4];
    const float* b2    = (const float*)d_in[5];
    const float* gamma = (const float*)d_in[6];
    const float* beta  = (const float*)d_in[7];
    float* out = (float*)d_out;

    cudaFuncSetAttribute(gcn_mma, cudaFuncAttributeMaxDynamicSharedMemorySize,
                         DSMEM_BYTES);

    prep_kernel<<<1, 128>>>(eiw, W2, b1);
    w12_kernel<<<C_, C_>>>(W1, W2);
    gcn_mma<<<NBLOCKS, 256, DSMEM_BYTES>>>(x, b2, out);
    stats_kernel<<<1, 128>>>(gamma, beta);
    norm_kernel<<<(G_*N_*C_)/4/256, 256>>>(out);
}